// round 1
// baseline (speedup 1.0000x reference)
#include <cuda_runtime.h>
#include <math.h>

typedef unsigned long long ull;

#define N_LEVELS 16
#define N_ENC    65536

struct ResArr { int r[N_LEVELS]; };

// ---------- packed f32x2 helpers (sm_100+) ----------
__device__ __forceinline__ ull pack2(float a) {
    ull r; asm("mov.b64 %0, {%1, %1};" : "=l"(r) : "f"(a)); return r;
}
__device__ __forceinline__ void fma2(ull& acc, ull a2, ull w2) {
    asm("fma.rn.f32x2 %0, %1, %2, %0;" : "+l"(acc) : "l"(a2), "l"(w2));
}
__device__ __forceinline__ float lo32(ull v){ return __uint_as_float((unsigned)v); }
__device__ __forceinline__ float hi32(ull v){ return __uint_as_float((unsigned)(v >> 32)); }

// ---------- SMEM layout (floats) ----------
#define O_DW1 0
#define O_DW2 2048
#define O_DW3 6144
#define O_CW1 7168
#define O_CW2 8192
#define O_CW3 12288
#define O_CW4 16384
#define O_DB1 16576
#define O_DB2 16640
#define O_DB3 16704
#define O_CB1 16720
#define O_CB2 16784
#define O_CB3 16848
#define O_CB4 16912
#define SMEM_FLOATS 16928   // padded to 16B multiple

// Dense layer: out[NOUT] = (relu?)(a[NIN] @ W + b). W row-major (NIN, NOUT).
// Weights read from SMEM as 16B broadcasts; math in packed f32x2.
template<int NIN, int NOUT, bool RELU>
__device__ __forceinline__ void dense_layer(const float* __restrict__ a,
                                            const float* __restrict__ W,
                                            const float* __restrict__ bias,
                                            float* __restrict__ out)
{
    static_assert(NOUT % 16 == 0, "NOUT tile");
    #pragma unroll
    for (int j0 = 0; j0 < NOUT; j0 += 16) {
        ull acc[8];
        {
            const ulonglong2* bp = reinterpret_cast<const ulonglong2*>(bias + j0);
            #pragma unroll
            for (int q = 0; q < 4; q++) { ulonglong2 t = bp[q]; acc[2*q] = t.x; acc[2*q+1] = t.y; }
        }
        #pragma unroll
        for (int k = 0; k < NIN; k++) {
            ull a2 = pack2(a[k]);
            const ulonglong2* wp = reinterpret_cast<const ulonglong2*>(W + k*NOUT + j0);
            #pragma unroll
            for (int q = 0; q < 4; q++) {
                ulonglong2 t = wp[q];
                fma2(acc[2*q],   a2, t.x);
                fma2(acc[2*q+1], a2, t.y);
            }
        }
        #pragma unroll
        for (int p = 0; p < 8; p++) {
            float lo = lo32(acc[p]), hi = hi32(acc[p]);
            if (RELU) { lo = fmaxf(lo, 0.f); hi = fmaxf(hi, 0.f); }
            out[j0 + 2*p]     = lo;
            out[j0 + 2*p + 1] = hi;
        }
    }
}

extern "C" __global__ void __launch_bounds__(256)
nerf_fused(const float* __restrict__ gx, const float* __restrict__ gtab,
           const float* __restrict__ w_dw1, const float* __restrict__ w_db1,
           const float* __restrict__ w_dw2, const float* __restrict__ w_db2,
           const float* __restrict__ w_dw3, const float* __restrict__ w_db3,
           const float* __restrict__ w_cw1, const float* __restrict__ w_cb1,
           const float* __restrict__ w_cw2, const float* __restrict__ w_cb2,
           const float* __restrict__ w_cw3, const float* __restrict__ w_cb3,
           const float* __restrict__ w_cw4, const float* __restrict__ w_cb4,
           float* __restrict__ out, int n, ResArr R)
{
    extern __shared__ float sm[];

    // cooperative weight staging
    for (int t = threadIdx.x; t < 2048; t += blockDim.x) sm[O_DW1 + t] = w_dw1[t];
    for (int t = threadIdx.x; t < 4096; t += blockDim.x) sm[O_DW2 + t] = w_dw2[t];
    for (int t = threadIdx.x; t < 1024; t += blockDim.x) sm[O_DW3 + t] = w_dw3[t];
    for (int t = threadIdx.x; t < 1024; t += blockDim.x) sm[O_CW1 + t] = w_cw1[t];
    for (int t = threadIdx.x; t < 4096; t += blockDim.x) sm[O_CW2 + t] = w_cw2[t];
    for (int t = threadIdx.x; t < 4096; t += blockDim.x) sm[O_CW3 + t] = w_cw3[t];
    for (int t = threadIdx.x; t < 192;  t += blockDim.x) sm[O_CW4 + t] = w_cw4[t];
    for (int t = threadIdx.x; t < 64;   t += blockDim.x) sm[O_DB1 + t] = w_db1[t];
    for (int t = threadIdx.x; t < 64;   t += blockDim.x) sm[O_DB2 + t] = w_db2[t];
    for (int t = threadIdx.x; t < 16;   t += blockDim.x) sm[O_DB3 + t] = w_db3[t];
    for (int t = threadIdx.x; t < 64;   t += blockDim.x) sm[O_CB1 + t] = w_cb1[t];
    for (int t = threadIdx.x; t < 64;   t += blockDim.x) sm[O_CB2 + t] = w_cb2[t];
    for (int t = threadIdx.x; t < 64;   t += blockDim.x) sm[O_CB3 + t] = w_cb3[t];
    for (int t = threadIdx.x; t < 3;    t += blockDim.x) sm[O_CB4 + t] = w_cb4[t];
    __syncthreads();

    int i = blockIdx.x * blockDim.x + threadIdx.x;
    if (i >= n) return;

    const float px = gx[3*i], py = gx[3*i+1], pz = gx[3*i+2];
    const float ux = px * 0.5f + 0.5f;
    const float uy = py * 0.5f + 0.5f;
    const float uz = pz * 0.5f + 0.5f;

    // ---------------- hash-grid encoding ----------------
    float h[32];
    #pragma unroll
    for (int l = 0; l < N_LEVELS; l++) {
        const int res = R.r[l];
        const float rm1 = (float)(res - 1);
        float qx = ux * rm1, qy = uy * rm1, qz = uz * rm1;
        int cx = (int)floorf(qx); cx = max(0, min(cx, res - 2));
        int cy = (int)floorf(qy); cy = max(0, min(cy, res - 2));
        int cz = (int)floorf(qz); cz = max(0, min(cz, res - 2));
        float wx = qx - (float)cx, wy = qy - (float)cy, wz = qz - (float)cz;
        float mx = 1.f - wx, my = 1.f - wy, mz = 1.f - wz;

        const float2* tab = reinterpret_cast<const float2*>(gtab) + ((size_t)l << 16);
        const bool dense = ((long long)res * res * res) <= (long long)N_ENC;

        float f0 = 0.f, f1 = 0.f;
        #pragma unroll
        for (int c8 = 0; c8 < 8; c8++) {
            const int ox = (c8 >> 2) & 1, oy = (c8 >> 1) & 1, oz = c8 & 1;
            const unsigned ix = (unsigned)(cx + ox);
            const unsigned iy = (unsigned)(cy + oy);
            const unsigned iz = (unsigned)(cz + oz);
            const float wc = (ox ? wx : mx) * (oy ? wy : my) * (oz ? wz : mz);
            unsigned idx;
            if (dense) {
                idx = ix + (unsigned)res * (iy + (unsigned)res * iz);
            } else {
                idx = (ix * 1u ^ iy * 2654435761u ^ iz * 805459861u) & 65535u;
            }
            const float2 e = __ldg(tab + idx);
            f0 = fmaf(wc, e.x, f0);
            f1 = fmaf(wc, e.y, f1);
        }
        h[2*l]     = f0;
        h[2*l + 1] = f1;
    }

    // ---------------- MLP ----------------
    float a1[64];  dense_layer<32, 64, true >(h,   sm + O_DW1, sm + O_DB1, a1);
    float a2[64];  dense_layer<64, 64, true >(a1,  sm + O_DW2, sm + O_DB2, a2);
    float dv[16];  dense_layer<64, 16, false>(a2,  sm + O_DW3, sm + O_DB3, dv);
    float c1[64];  dense_layer<16, 64, true >(dv,  sm + O_CW1, sm + O_CB1, c1);
    float c2[64];  dense_layer<64, 64, true >(c1,  sm + O_CW2, sm + O_CB2, c2);
    float c3[64];  dense_layer<64, 64, true >(c2,  sm + O_CW3, sm + O_CB3, c3);

    float o0 = sm[O_CB4 + 0], o1 = sm[O_CB4 + 1], o2 = sm[O_CB4 + 2];
    #pragma unroll
    for (int k = 0; k < 64; k++) {
        const float av = c3[k];
        o0 = fmaf(av, sm[O_CW4 + 3*k + 0], o0);
        o1 = fmaf(av, sm[O_CW4 + 3*k + 1], o1);
        o2 = fmaf(av, sm[O_CW4 + 3*k + 2], o2);
    }

    out[i] = expf(dv[0]);                               // sigma
    out[n + 3*i + 0] = 1.f / (1.f + expf(-o0));         // color (sigmoid)
    out[n + 3*i + 1] = 1.f / (1.f + expf(-o1));
    out[n + 3*i + 2] = 1.f / (1.f + expf(-o2));
}

extern "C" void kernel_launch(void* const* d_in, const int* in_sizes, int n_in,
                              void* d_out, int out_size)
{
    const float* x    = (const float*)d_in[0];
    const float* tab  = (const float*)d_in[1];
    const float* dw1  = (const float*)d_in[2];
    const float* db1  = (const float*)d_in[3];
    const float* dw2  = (const float*)d_in[4];
    const float* db2  = (const float*)d_in[5];
    const float* dw3  = (const float*)d_in[6];
    const float* db3  = (const float*)d_in[7];
    const float* cw1  = (const float*)d_in[8];
    const float* cb1  = (const float*)d_in[9];
    const float* cw2  = (const float*)d_in[10];
    const float* cb2  = (const float*)d_in[11];
    const float* cw3  = (const float*)d_in[12];
    const float* cb3  = (const float*)d_in[13];
    const float* cw4  = (const float*)d_in[14];
    const float* cb4  = (const float*)d_in[15];

    const int n = in_sizes[0] / 3;

    // Replicate numpy's double-precision RES computation exactly (same libm).
    ResArr R;
    const double growth = exp((log(512.0) - log(16.0)) / 15.0);
    for (int l = 0; l < N_LEVELS; l++)
        R.r[l] = (int)floor(16.0 * pow(growth, (double)l));

    const size_t smem = SMEM_FLOATS * sizeof(float);
    cudaFuncSetAttribute(nerf_fused, cudaFuncAttributeMaxDynamicSharedMemorySize, (int)smem);

    const int threads = 256;
    const int blocks = (n + threads - 1) / threads;
    nerf_fused<<<blocks, threads, smem>>>(
        x, tab, dw1, db1, dw2, db2, dw3, db3,
        cw1, cb1, cw2, cb2, cw3, cb3, cw4, cb4,
        (float*)d_out, n, R);
}

// round 2
// speedup vs baseline: 1.3613x; 1.3613x over previous
#include <cuda_runtime.h>
#include <math.h>

typedef unsigned long long ull;

#define NPTS_CTA 128          // points per CTA
#define NTHR     256

// ---------- packed f32x2 helpers (sm_100+) ----------
__device__ __forceinline__ ull pack2(float a) {
    ull r; asm("mov.b64 %0, {%1, %1};" : "=l"(r) : "f"(a)); return r;
}
__device__ __forceinline__ void fma2(ull& acc, ull a2, ull w2) {
    asm("fma.rn.f32x2 %0, %1, %2, %0;" : "+l"(acc) : "l"(a2), "l"(w2));
}
__device__ __forceinline__ float lo32(ull v){ return __uint_as_float((unsigned)v); }
__device__ __forceinline__ float hi32(ull v){ return __uint_as_float((unsigned)(v >> 32)); }

// ---------- SMEM layout (float offsets) ----------
#define SB0   0         // act buffer 0: 64 x 128 floats
#define SB1   8192      // act buffer 1: 64 x 128 floats
#define SWGT  16384     // weight stage: up to 4096 floats (64x64)
#define SBIA  20480     // bias stage: 64 floats
#define SMEMF 20544
#define SMEMB (SMEMF * 4)

// Compile-time level resolutions (validated numerically by the passing R1 kernel,
// which computed the identical table host-side with double libm).
// res^3 <= 65536  <=>  res <= 40  => levels 0..4 dense, 5..15 hashed.
__device__ constexpr int RESV[16] =
    {16, 20, 25, 32, 40, 50, 64, 80, 101, 128, 161, 203, 256, 322, 406, 512};

// cooperative stage: global -> smem (count must be multiple of 4)
__device__ __forceinline__ void stage4(const float* __restrict__ g, float* s,
                                       int count, int tid) {
    const float4* g4 = reinterpret_cast<const float4*>(g);
    float4* s4 = reinterpret_cast<float4*>(s);
    for (int i = tid; i < (count >> 2); i += NTHR) s4[i] = __ldg(g4 + i);
}

// ---------------- hash-grid encode: 8 levels starting at L0 ----------------
template<int L0>
__device__ __forceinline__ void encode8(float ux, float uy, float uz,
                                        const float* __restrict__ gtab,
                                        float* __restrict__ sm, int p, bool valid)
{
    #pragma unroll
    for (int ll = 0; ll < 8; ll++) {
        constexpr_helper:;
        const int l = L0 + ll;
        const int res = RESV[l];
        const bool dense = ((long long)res * res * res) <= 65536LL;
        float f0 = 0.f, f1 = 0.f;
        if (valid) {
            const float rm1 = (float)(res - 1);
            float qx = ux * rm1, qy = uy * rm1, qz = uz * rm1;
            int cx = (int)floorf(qx); cx = max(0, min(cx, res - 2));
            int cy = (int)floorf(qy); cy = max(0, min(cy, res - 2));
            int cz = (int)floorf(qz); cz = max(0, min(cz, res - 2));
            float wx = qx - (float)cx, wy = qy - (float)cy, wz = qz - (float)cz;
            float mx = 1.f - wx, my = 1.f - wy, mz = 1.f - wz;
            const float2* tab = reinterpret_cast<const float2*>(gtab) + ((size_t)l << 16);
            #pragma unroll
            for (int c8 = 0; c8 < 8; c8++) {
                const int ox = (c8 >> 2) & 1, oy = (c8 >> 1) & 1, oz = c8 & 1;
                const unsigned ix = (unsigned)(cx + ox);
                const unsigned iy = (unsigned)(cy + oy);
                const unsigned iz = (unsigned)(cz + oz);
                const float wc = (ox ? wx : mx) * (oy ? wy : my) * (oz ? wz : mz);
                unsigned idx;
                if (dense) idx = ix + (unsigned)res * (iy + (unsigned)res * iz);
                else       idx = (ix * 1u ^ iy * 2654435761u ^ iz * 805459861u) & 65535u;
                const float2 e = __ldg(tab + idx);
                f0 = fmaf(wc, e.x, f0);
                f1 = fmaf(wc, e.y, f1);
            }
        }
        sm[(2*l)     * NPTS_CTA + p] = f0;
        sm[(2*l + 1) * NPTS_CTA + p] = f1;
    }
}

// ---------------- GEMM layer, NOUT = 64 ----------------
// src/dst: feature-major act tiles [feat][128]. Weights+bias already staged in smem.
template<int NIN, bool RELU>
__device__ __forceinline__ void layer64(const float* __restrict__ smf,
                                        const float* __restrict__ src,
                                        float* __restrict__ dst, int tid)
{
    const int pg = tid & 63;            // point-group (2 points)
    const int j0 = (tid >> 6) << 4;     // output tile start (warp-uniform)

    const float* wsm = smf + SWGT;
    const ulonglong2* bia = reinterpret_cast<const ulonglong2*>(smf + SBIA + j0);

    ull acc[16];
    #pragma unroll
    for (int q = 0; q < 4; q++) {
        ulonglong2 b = bia[q];
        acc[2*q] = b.x;  acc[2*q+1] = b.y;
        acc[8+2*q] = b.x; acc[8+2*q+1] = b.y;
    }

    const float2* A2 = reinterpret_cast<const float2*>(src);
    #pragma unroll
    for (int k = 0; k < NIN; k++) {
        float2 a = A2[k * 64 + pg];
        ull a0 = pack2(a.x), a1 = pack2(a.y);
        const ulonglong2* wr = reinterpret_cast<const ulonglong2*>(wsm + k*64 + j0);
        ulonglong2 w0 = wr[0], w1 = wr[1], w2 = wr[2], w3 = wr[3];
        fma2(acc[0], a0, w0.x); fma2(acc[1], a0, w0.y);
        fma2(acc[2], a0, w1.x); fma2(acc[3], a0, w1.y);
        fma2(acc[4], a0, w2.x); fma2(acc[5], a0, w2.y);
        fma2(acc[6], a0, w3.x); fma2(acc[7], a0, w3.y);
        fma2(acc[8],  a1, w0.x); fma2(acc[9],  a1, w0.y);
        fma2(acc[10], a1, w1.x); fma2(acc[11], a1, w1.y);
        fma2(acc[12], a1, w2.x); fma2(acc[13], a1, w2.y);
        fma2(acc[14], a1, w3.x); fma2(acc[15], a1, w3.y);
    }

    float2* D2 = reinterpret_cast<float2*>(dst);
    #pragma unroll
    for (int q = 0; q < 8; q++) {
        float v00 = lo32(acc[q]),   v01 = hi32(acc[q]);
        float v10 = lo32(acc[8+q]), v11 = hi32(acc[8+q]);
        if (RELU) {
            v00 = fmaxf(v00, 0.f); v01 = fmaxf(v01, 0.f);
            v10 = fmaxf(v10, 0.f); v11 = fmaxf(v11, 0.f);
        }
        D2[(j0 + 2*q)     * 64 + pg] = make_float2(v00, v10);
        D2[(j0 + 2*q + 1) * 64 + pg] = make_float2(v01, v11);
    }
}

// ---------------- density head: NIN=64, NOUT=16, no relu, emits sigma ----------------
__device__ __forceinline__ void layer_d(const float* __restrict__ smf,
                                        const float* __restrict__ src,
                                        float* __restrict__ dst,
                                        float* __restrict__ out,
                                        int tid, int gbase, int n)
{
    const int pg = tid;  // tid < 64

    const float* wsm = smf + SWGT;
    const ulonglong2* bia = reinterpret_cast<const ulonglong2*>(smf + SBIA);

    ull acc[16];
    #pragma unroll
    for (int q = 0; q < 4; q++) {
        ulonglong2 b = bia[q];
        acc[2*q] = b.x;  acc[2*q+1] = b.y;
        acc[8+2*q] = b.x; acc[8+2*q+1] = b.y;
    }

    const float2* A2 = reinterpret_cast<const float2*>(src);
    #pragma unroll
    for (int k = 0; k < 64; k++) {
        float2 a = A2[k * 64 + pg];
        ull a0 = pack2(a.x), a1 = pack2(a.y);
        const ulonglong2* wr = reinterpret_cast<const ulonglong2*>(wsm + k*16);
        ulonglong2 w0 = wr[0], w1 = wr[1], w2 = wr[2], w3 = wr[3];
        fma2(acc[0], a0, w0.x); fma2(acc[1], a0, w0.y);
        fma2(acc[2], a0, w1.x); fma2(acc[3], a0, w1.y);
        fma2(acc[4], a0, w2.x); fma2(acc[5], a0, w2.y);
        fma2(acc[6], a0, w3.x); fma2(acc[7], a0, w3.y);
        fma2(acc[8],  a1, w0.x); fma2(acc[9],  a1, w0.y);
        fma2(acc[10], a1, w1.x); fma2(acc[11], a1, w1.y);
        fma2(acc[12], a1, w2.x); fma2(acc[13], a1, w2.y);
        fma2(acc[14], a1, w3.x); fma2(acc[15], a1, w3.y);
    }

    float2* D2 = reinterpret_cast<float2*>(dst);
    #pragma unroll
    for (int q = 0; q < 8; q++) {
        D2[(2*q)     * 64 + pg] = make_float2(lo32(acc[q]),   lo32(acc[8+q]));
        D2[(2*q + 1) * 64 + pg] = make_float2(hi32(acc[q]),   hi32(acc[8+q]));
    }

    // sigma = exp(d[:,0])
    int g0 = gbase + 2*pg, g1 = gbase + 2*pg + 1;
    if (g0 < n) out[g0] = expf(lo32(acc[0]));
    if (g1 < n) out[g1] = expf(lo32(acc[8]));
}

extern "C" __global__ void __launch_bounds__(NTHR, 2)
nerf_fused2(const float* __restrict__ gx, const float* __restrict__ gtab,
            const float* __restrict__ w_dw1, const float* __restrict__ w_db1,
            const float* __restrict__ w_dw2, const float* __restrict__ w_db2,
            const float* __restrict__ w_dw3, const float* __restrict__ w_db3,
            const float* __restrict__ w_cw1, const float* __restrict__ w_cb1,
            const float* __restrict__ w_cw2, const float* __restrict__ w_cb2,
            const float* __restrict__ w_cw3, const float* __restrict__ w_cb3,
            const float* __restrict__ w_cw4, const float* __restrict__ w_cb4,
            float* __restrict__ out, int n)
{
    extern __shared__ float smf[];
    const int tid = threadIdx.x;
    const int gbase = blockIdx.x * NPTS_CTA;

    // ---- stage layer-1 weights, then encode ----
    stage4(w_dw1, smf + SWGT, 32*64, tid);
    stage4(w_db1, smf + SBIA, 64, tid);

    {
        const int p = tid & (NPTS_CTA - 1);
        const int half = tid >> 7;
        const int gp = gbase + p;
        const bool valid = gp < n;
        float px = 0.f, py = 0.f, pz = 0.f;
        if (valid) { px = gx[3*gp]; py = gx[3*gp+1]; pz = gx[3*gp+2]; }
        const float ux = px * 0.5f + 0.5f;
        const float uy = py * 0.5f + 0.5f;
        const float uz = pz * 0.5f + 0.5f;
        if (half == 0) encode8<0>(ux, uy, uz, gtab, smf + SB0, p, valid);
        else           encode8<8>(ux, uy, uz, gtab, smf + SB0, p, valid);
    }
    __syncthreads();

    // d1: 32 -> 64, relu
    layer64<32, true>(smf, smf + SB0, smf + SB1, tid);
    __syncthreads();
    stage4(w_dw2, smf + SWGT, 64*64, tid);
    stage4(w_db2, smf + SBIA, 64, tid);
    __syncthreads();

    // d2: 64 -> 64, relu
    layer64<64, true>(smf, smf + SB1, smf + SB0, tid);
    __syncthreads();
    stage4(w_dw3, smf + SWGT, 64*16, tid);
    stage4(w_db3, smf + SBIA, 16, tid);
    __syncthreads();

    // d3: 64 -> 16, no relu, sigma out
    if (tid < 64)
        layer_d(smf, smf + SB0, smf + SB1, out, tid, gbase, n);
    __syncthreads();
    stage4(w_cw1, smf + SWGT, 16*64, tid);
    stage4(w_cb1, smf + SBIA, 64, tid);
    __syncthreads();

    // c1: 16 -> 64, relu
    layer64<16, true>(smf, smf + SB1, smf + SB0, tid);
    __syncthreads();
    stage4(w_cw2, smf + SWGT, 64*64, tid);
    stage4(w_cb2, smf + SBIA, 64, tid);
    __syncthreads();

    // c2: 64 -> 64, relu
    layer64<64, true>(smf, smf + SB0, smf + SB1, tid);
    __syncthreads();
    stage4(w_cw3, smf + SWGT, 64*64, tid);
    stage4(w_cb3, smf + SBIA, 64, tid);
    __syncthreads();

    // c3: 64 -> 64, relu
    layer64<64, true>(smf, smf + SB1, smf + SB0, tid);
    __syncthreads();
    stage4(w_cw4, smf + SWGT, 192, tid);
    if (tid < 3) smf[SBIA + tid] = __ldg(w_cb4 + tid);
    __syncthreads();

    // color head: 64 -> 3, sigmoid
    if (tid < NPTS_CTA) {
        const int p = tid;
        const int gp = gbase + p;
        const float* A = smf + SB0;
        const float* cw = smf + SWGT;
        float s0 = smf[SBIA + 0], s1 = smf[SBIA + 1], s2 = smf[SBIA + 2];
        #pragma unroll
        for (int k = 0; k < 64; k++) {
            float a = A[k * NPTS_CTA + p];
            s0 = fmaf(a, cw[3*k + 0], s0);
            s1 = fmaf(a, cw[3*k + 1], s1);
            s2 = fmaf(a, cw[3*k + 2], s2);
        }
        if (gp < n) {
            out[n + 3*gp + 0] = 1.f / (1.f + expf(-s0));
            out[n + 3*gp + 1] = 1.f / (1.f + expf(-s1));
            out[n + 3*gp + 2] = 1.f / (1.f + expf(-s2));
        }
    }
}

extern "C" void kernel_launch(void* const* d_in, const int* in_sizes, int n_in,
                              void* d_out, int out_size)
{
    const float* x    = (const float*)d_in[0];
    const float* tab  = (const float*)d_in[1];
    const float* dw1  = (const float*)d_in[2];
    const float* db1  = (const float*)d_in[3];
    const float* dw2  = (const float*)d_in[4];
    const float* db2  = (const float*)d_in[5];
    const float* dw3  = (const float*)d_in[6];
    const float* db3  = (const float*)d_in[7];
    const float* cw1  = (const float*)d_in[8];
    const float* cb1  = (const float*)d_in[9];
    const float* cw2  = (const float*)d_in[10];
    const float* cb2  = (const float*)d_in[11];
    const float* cw3  = (const float*)d_in[12];
    const float* cb3  = (const float*)d_in[13];
    const float* cw4  = (const float*)d_in[14];
    const float* cb4  = (const float*)d_in[15];

    const int n = in_sizes[0] / 3;

    static int configured = -1;
    if (configured < 0) {
        cudaFuncSetAttribute(nerf_fused2,
                             cudaFuncAttributeMaxDynamicSharedMemorySize, SMEMB);
        configured = 1;
    }

    const int blocks = (n + NPTS_CTA - 1) / NPTS_CTA;
    nerf_fused2<<<blocks, NTHR, SMEMB>>>(
        x, tab, dw1, db1, dw2, db2, dw3, db3,
        cw1, cb1, cw2, cb2, cw3, cb3, cw4, cb4,
        (float*)d_out, n);
}

// round 3
// speedup vs baseline: 1.5695x; 1.1529x over previous
#include <cuda_runtime.h>
#include <math.h>

typedef unsigned long long ull;

#define NPTS_CTA 256
#define NTHR     256

// ---------- packed f32x2 helpers (sm_100+) ----------
__device__ __forceinline__ ull pack2(float a) {
    ull r; asm("mov.b64 %0, {%1, %1};" : "=l"(r) : "f"(a)); return r;
}
__device__ __forceinline__ void fma2(ull& acc, ull a2, ull w2) {
    asm("fma.rn.f32x2 %0, %1, %2, %0;" : "+l"(acc) : "l"(a2), "l"(w2));
}
__device__ __forceinline__ float lo32(ull v){ return __uint_as_float((unsigned)v); }
__device__ __forceinline__ float hi32(ull v){ return __uint_as_float((unsigned)(v >> 32)); }

// ---------- SMEM layout (float offsets) ----------
#define SACT  0          // in-place act buffer: 64 x 256 floats
#define SW0   16384      // weight buffer 0 (4096)
#define SW1   20480      // weight buffer 1 (4096)
#define SBI0  24576      // bias buffer 0 (64)
#define SBI1  24640      // bias buffer 1 (64)
#define SMEMF 24704
#define SMEMB (SMEMF * 4)

// Level resolutions (validated numerically by the passing R1 kernel, which
// computed the identical values host-side with double libm).
// res^3 <= 65536 <=> res <= 40 => levels 0..4 dense, 5..15 hashed.
__device__ constexpr int RESV[16] =
    {16, 20, 25, 32, 40, 50, 64, 80, 101, 128, 161, 203, 256, 322, 406, 512};

__device__ __forceinline__ void stage4(const float* __restrict__ g, float* s,
                                       int count, int tid) {
    const float4* g4 = reinterpret_cast<const float4*>(g);
    float4* s4 = reinterpret_cast<float4*>(s);
    #pragma unroll
    for (int i = tid; i < (count >> 2); i += NTHR) s4[i] = __ldg(g4 + i);
}

// ---------------- hash-grid encode: all 16 levels, one thread per point ----
__device__ __forceinline__ void encode16(float ux, float uy, float uz,
                                         const float* __restrict__ gtab,
                                         float* __restrict__ sm, int p, bool valid)
{
    #pragma unroll
    for (int l = 0; l < 16; l++) {
        const int res = RESV[l];
        const bool dense = ((long long)res * res * res) <= 65536LL;
        float f0 = 0.f, f1 = 0.f;
        if (valid) {
            const float rm1 = (float)(res - 1);
            float qx = ux * rm1, qy = uy * rm1, qz = uz * rm1;
            int cx = (int)floorf(qx); cx = max(0, min(cx, res - 2));
            int cy = (int)floorf(qy); cy = max(0, min(cy, res - 2));
            int cz = (int)floorf(qz); cz = max(0, min(cz, res - 2));
            float wx = qx - (float)cx, wy = qy - (float)cy, wz = qz - (float)cz;
            float mx = 1.f - wx, my = 1.f - wy, mz = 1.f - wz;
            const float2* tab = reinterpret_cast<const float2*>(gtab) + ((size_t)l << 16);
            #pragma unroll
            for (int c8 = 0; c8 < 8; c8++) {
                const int ox = (c8 >> 2) & 1, oy = (c8 >> 1) & 1, oz = c8 & 1;
                const unsigned ix = (unsigned)(cx + ox);
                const unsigned iy = (unsigned)(cy + oy);
                const unsigned iz = (unsigned)(cz + oz);
                const float wc = (ox ? wx : mx) * (oy ? wy : my) * (oz ? wz : mz);
                unsigned idx;
                if (dense) idx = ix + (unsigned)res * (iy + (unsigned)res * iz);
                else       idx = (ix * 1u ^ iy * 2654435761u ^ iz * 805459861u) & 65535u;
                const float2 e = __ldg(tab + idx);
                f0 = fmaf(wc, e.x, f0);
                f1 = fmaf(wc, e.y, f1);
            }
        }
        sm[(2*l)     * NPTS_CTA + p] = f0;
        sm[(2*l + 1) * NPTS_CTA + p] = f1;
    }
}

// ---------------- in-place GEMM layer ----------------
// acts feature-major [feat][256] in SACT. Thread = 4-pt group x (NOUT/4) outputs.
// EMIT_SIGMA: strip-0 threads write exp(out0) for their 4 points.
template<int NIN, int NOUT, bool RELU, bool EMIT_SIGMA>
__device__ __forceinline__ void layer(float* __restrict__ smf,
                                      const float* __restrict__ W,
                                      const float* __restrict__ bias,
                                      int tid, float* __restrict__ out,
                                      int gbase, int n)
{
    constexpr int SP = NOUT / 4;      // outputs per thread
    constexpr int PAIRS = SP / 2;     // f32x2 pairs per point
    const int pg = tid & 63;          // 4-point group
    const int strip = tid >> 6;
    const int j0 = strip * SP;        // warp-uniform

    ull acc[4][PAIRS];
    {
        const ull* bp = reinterpret_cast<const ull*>(bias + j0);
        #pragma unroll
        for (int q = 0; q < PAIRS; q++) {
            ull b = bp[q];
            acc[0][q] = b; acc[1][q] = b; acc[2][q] = b; acc[3][q] = b;
        }
    }

    const float4* A4 = reinterpret_cast<const float4*>(smf + SACT);
    #pragma unroll
    for (int k = 0; k < NIN; k++) {
        float4 a = A4[k * 64 + pg];
        ull a0 = pack2(a.x), a1 = pack2(a.y), a2 = pack2(a.z), a3 = pack2(a.w);
        const ulonglong2* wr = reinterpret_cast<const ulonglong2*>(W + k*NOUT + j0);
        #pragma unroll
        for (int q2 = 0; q2 < PAIRS/2; q2++) {
            ulonglong2 w = wr[q2];
            fma2(acc[0][2*q2],   a0, w.x); fma2(acc[0][2*q2+1], a0, w.y);
            fma2(acc[1][2*q2],   a1, w.x); fma2(acc[1][2*q2+1], a1, w.y);
            fma2(acc[2][2*q2],   a2, w.x); fma2(acc[2][2*q2+1], a2, w.y);
            fma2(acc[3][2*q2],   a3, w.x); fma2(acc[3][2*q2+1], a3, w.y);
        }
    }

    __syncthreads();   // all reads of SACT done -> safe to overwrite in place

    float4* D4 = reinterpret_cast<float4*>(smf + SACT);
    #pragma unroll
    for (int q = 0; q < PAIRS; q++) {
        float v0l = lo32(acc[0][q]), v0h = hi32(acc[0][q]);
        float v1l = lo32(acc[1][q]), v1h = hi32(acc[1][q]);
        float v2l = lo32(acc[2][q]), v2h = hi32(acc[2][q]);
        float v3l = lo32(acc[3][q]), v3h = hi32(acc[3][q]);
        if (RELU) {
            v0l = fmaxf(v0l, 0.f); v0h = fmaxf(v0h, 0.f);
            v1l = fmaxf(v1l, 0.f); v1h = fmaxf(v1h, 0.f);
            v2l = fmaxf(v2l, 0.f); v2h = fmaxf(v2h, 0.f);
            v3l = fmaxf(v3l, 0.f); v3h = fmaxf(v3h, 0.f);
        }
        D4[(j0 + 2*q)     * 64 + pg] = make_float4(v0l, v1l, v2l, v3l);
        D4[(j0 + 2*q + 1) * 64 + pg] = make_float4(v0h, v1h, v2h, v3h);
    }

    if (EMIT_SIGMA && strip == 0) {
        const int g0 = gbase + 4*pg;
        float s0 = lo32(acc[0][0]), s1 = lo32(acc[1][0]);
        float s2 = lo32(acc[2][0]), s3 = lo32(acc[3][0]);
        if (g0 + 0 < n) out[g0 + 0] = expf(s0);
        if (g0 + 1 < n) out[g0 + 1] = expf(s1);
        if (g0 + 2 < n) out[g0 + 2] = expf(s2);
        if (g0 + 3 < n) out[g0 + 3] = expf(s3);
    }
}

extern "C" __global__ void __launch_bounds__(NTHR, 2)
nerf_fused3(const float* __restrict__ gx, const float* __restrict__ gtab,
            const float* __restrict__ w_dw1, const float* __restrict__ w_db1,
            const float* __restrict__ w_dw2, const float* __restrict__ w_db2,
            const float* __restrict__ w_dw3, const float* __restrict__ w_db3,
            const float* __restrict__ w_cw1, const float* __restrict__ w_cb1,
            const float* __restrict__ w_cw2, const float* __restrict__ w_cb2,
            const float* __restrict__ w_cw3, const float* __restrict__ w_cb3,
            const float* __restrict__ w_cw4, const float* __restrict__ w_cb4,
            float* __restrict__ out, int n)
{
    extern __shared__ float smf[];
    const int tid = threadIdx.x;
    const int gbase = blockIdx.x * NPTS_CTA;

    // stage layer-1 weights (overlaps with encode)
    stage4(w_dw1, smf + SW0, 32*64, tid);
    stage4(w_db1, smf + SBI0, 64, tid);

    {
        const int p = tid;
        const int gp = gbase + p;
        const bool valid = gp < n;
        float px = 0.f, py = 0.f, pz = 0.f;
        if (valid) { px = gx[3*gp]; py = gx[3*gp+1]; pz = gx[3*gp+2]; }
        encode16(px * 0.5f + 0.5f, py * 0.5f + 0.5f, pz * 0.5f + 0.5f,
                 gtab, smf + SACT, p, valid);
    }
    __syncthreads();

    // d1: 32 -> 64 relu
    stage4(w_dw2, smf + SW1, 64*64, tid);
    stage4(w_db2, smf + SBI1, 64, tid);
    layer<32, 64, true, false>(smf, smf + SW0, smf + SBI0, tid, (float*)out, gbase, n);
    __syncthreads();

    // d2: 64 -> 64 relu
    stage4(w_dw3, smf + SW0, 64*16, tid);
    stage4(w_db3, smf + SBI0, 16, tid);
    layer<64, 64, true, false>(smf, smf + SW1, smf + SBI1, tid, (float*)out, gbase, n);
    __syncthreads();

    // d3: 64 -> 16, no relu, emits sigma
    stage4(w_cw1, smf + SW1, 16*64, tid);
    stage4(w_cb1, smf + SBI1, 64, tid);
    layer<64, 16, false, true>(smf, smf + SW0, smf + SBI0, tid, (float*)out, gbase, n);
    __syncthreads();

    // c1: 16 -> 64 relu
    stage4(w_cw2, smf + SW0, 64*64, tid);
    stage4(w_cb2, smf + SBI0, 64, tid);
    layer<16, 64, true, false>(smf, smf + SW1, smf + SBI1, tid, (float*)out, gbase, n);
    __syncthreads();

    // c2: 64 -> 64 relu
    stage4(w_cw3, smf + SW1, 64*64, tid);
    stage4(w_cb3, smf + SBI1, 64, tid);
    layer<64, 64, true, false>(smf, smf + SW0, smf + SBI0, tid, (float*)out, gbase, n);
    __syncthreads();

    // c3: 64 -> 64 relu
    stage4(w_cw4, smf + SW0, 192, tid);
    if (tid < 3) smf[SBI0 + tid] = __ldg(w_cb4 + tid);
    layer<64, 64, true, false>(smf, smf + SW1, smf + SBI1, tid, (float*)out, gbase, n);
    __syncthreads();

    // color head: 64 -> 3, sigmoid; one thread per point
    {
        const int p = tid;
        const int gp = gbase + p;
        const float* A = smf + SACT;
        const float* cw = smf + SW0;
        float s0 = smf[SBI0 + 0], s1 = smf[SBI0 + 1], s2 = smf[SBI0 + 2];
        #pragma unroll
        for (int k = 0; k < 64; k++) {
            float a = A[k * NPTS_CTA + p];
            s0 = fmaf(a, cw[3*k + 0], s0);
            s1 = fmaf(a, cw[3*k + 1], s1);
            s2 = fmaf(a, cw[3*k + 2], s2);
        }
        if (gp < n) {
            out[n + 3*gp + 0] = 1.f / (1.f + expf(-s0));
            out[n + 3*gp + 1] = 1.f / (1.f + expf(-s1));
            out[n + 3*gp + 2] = 1.f / (1.f + expf(-s2));
        }
    }
}

extern "C" void kernel_launch(void* const* d_in, const int* in_sizes, int n_in,
                              void* d_out, int out_size)
{
    const float* x    = (const float*)d_in[0];
    const float* tab  = (const float*)d_in[1];
    const float* dw1  = (const float*)d_in[2];
    const float* db1  = (const float*)d_in[3];
    const float* dw2  = (const float*)d_in[4];
    const float* db2  = (const float*)d_in[5];
    const float* dw3  = (const float*)d_in[6];
    const float* db3  = (const float*)d_in[7];
    const float* cw1  = (const float*)d_in[8];
    const float* cb1  = (const float*)d_in[9];
    const float* cw2  = (const float*)d_in[10];
    const float* cb2  = (const float*)d_in[11];
    const float* cw3  = (const float*)d_in[12];
    const float* cb3  = (const float*)d_in[13];
    const float* cw4  = (const float*)d_in[14];
    const float* cb4  = (const float*)d_in[15];

    const int n = in_sizes[0] / 3;

    static int configured = -1;
    if (configured < 0) {
        cudaFuncSetAttribute(nerf_fused3,
                             cudaFuncAttributeMaxDynamicSharedMemorySize, SMEMB);
        configured = 1;
    }

    const int blocks = (n + NPTS_CTA - 1) / NPTS_CTA;
    nerf_fused3<<<blocks, NTHR, SMEMB>>>(
        x, tab, dw1, db1, dw2, db2, dw3, db3,
        cw1, cb1, cw2, cb2, cw3, cb3, cw4, cb4,
        (float*)d_out, n);
}

// round 4
// speedup vs baseline: 1.5698x; 1.0002x over previous
#include <cuda_runtime.h>
#include <math.h>

typedef unsigned long long ull;

#define NPTS_CTA 256
#define NTHR     256

// ---------- packed f32x2 helpers (sm_100+) ----------
__device__ __forceinline__ ull pack2(float a) {
    ull r; asm("mov.b64 %0, {%1, %1};" : "=l"(r) : "f"(a)); return r;
}
__device__ __forceinline__ void fma2(ull& acc, ull a2, ull w2) {
    asm("fma.rn.f32x2 %0, %1, %2, %0;" : "+l"(acc) : "l"(a2), "l"(w2));
}
__device__ __forceinline__ float lo32(ull v){ return __uint_as_float((unsigned)v); }
__device__ __forceinline__ float hi32(ull v){ return __uint_as_float((unsigned)(v >> 32)); }

// ---------- SMEM layout (float offsets) ----------
#define SACT  0          // in-place act buffer: 64 x 256 floats
#define SW0   16384      // weight buffer 0 (4096)
#define SW1   20480      // weight buffer 1 (4096)
#define SBI0  24576      // bias buffer 0 (64)
#define SBI1  24640      // bias buffer 1 (64)
#define SMEMF 24704
#define SMEMB (SMEMF * 4)

// Level resolutions (validated numerically by the passing R1 kernel, which
// computed the identical values host-side with double libm).
// res^3 <= 65536 <=> res <= 40 => levels 0..4 dense, 5..15 hashed.
__device__ constexpr int RESV[16] =
    {16, 20, 25, 32, 40, 50, 64, 80, 101, 128, 161, 203, 256, 322, 406, 512};

__device__ __forceinline__ void stage4(const float* __restrict__ g, float* s,
                                       int count, int tid) {
    const float4* g4 = reinterpret_cast<const float4*>(g);
    float4* s4 = reinterpret_cast<float4*>(s);
    #pragma unroll
    for (int i = tid; i < (count >> 2); i += NTHR) s4[i] = __ldg(g4 + i);
}

// ---------------- hash-grid encode: all 16 levels, one thread per point ----
__device__ __forceinline__ void encode16(float ux, float uy, float uz,
                                         const float* __restrict__ gtab,
                                         float* __restrict__ sm, int p, bool valid)
{
    #pragma unroll
    for (int l = 0; l < 16; l++) {
        const int res = RESV[l];
        const bool dense = ((long long)res * res * res) <= 65536LL;
        float f0 = 0.f, f1 = 0.f;
        if (valid) {
            const float rm1 = (float)(res - 1);
            float qx = ux * rm1, qy = uy * rm1, qz = uz * rm1;
            int cx = (int)floorf(qx); cx = max(0, min(cx, res - 2));
            int cy = (int)floorf(qy); cy = max(0, min(cy, res - 2));
            int cz = (int)floorf(qz); cz = max(0, min(cz, res - 2));
            float wx = qx - (float)cx, wy = qy - (float)cy, wz = qz - (float)cz;
            float mx = 1.f - wx, my = 1.f - wy, mz = 1.f - wz;
            const float2* tab = reinterpret_cast<const float2*>(gtab) + ((size_t)l << 16);
            #pragma unroll
            for (int c8 = 0; c8 < 8; c8++) {
                const int ox = (c8 >> 2) & 1, oy = (c8 >> 1) & 1, oz = c8 & 1;
                const unsigned ix = (unsigned)(cx + ox);
                const unsigned iy = (unsigned)(cy + oy);
                const unsigned iz = (unsigned)(cz + oz);
                const float wc = (ox ? wx : mx) * (oy ? wy : my) * (oz ? wz : mz);
                unsigned idx;
                if (dense) idx = ix + (unsigned)res * (iy + (unsigned)res * iz);
                else       idx = (ix * 1u ^ iy * 2654435761u ^ iz * 805459861u) & 65535u;
                const float2 e = __ldg(tab + idx);
                f0 = fmaf(wc, e.x, f0);
                f1 = fmaf(wc, e.y, f1);
            }
        }
        sm[(2*l)     * NPTS_CTA + p] = f0;
        sm[(2*l + 1) * NPTS_CTA + p] = f1;
    }
}

// ---------------- in-place GEMM layer ----------------
// acts feature-major [feat][256] in SACT. Thread = 4-pt group x (NOUT/4) outputs.
// EMIT_SIGMA: strip-0 threads write exp(out0) for their 4 points.
template<int NIN, int NOUT, bool RELU, bool EMIT_SIGMA>
__device__ __forceinline__ void layer(float* __restrict__ smf,
                                      const float* __restrict__ W,
                                      const float* __restrict__ bias,
                                      int tid, float* __restrict__ out,
                                      int gbase, int n)
{
    constexpr int SP = NOUT / 4;      // outputs per thread
    constexpr int PAIRS = SP / 2;     // f32x2 pairs per point
    const int pg = tid & 63;          // 4-point group
    const int strip = tid >> 6;
    const int j0 = strip * SP;        // warp-uniform

    ull acc[4][PAIRS];
    {
        const ull* bp = reinterpret_cast<const ull*>(bias + j0);
        #pragma unroll
        for (int q = 0; q < PAIRS; q++) {
            ull b = bp[q];
            acc[0][q] = b; acc[1][q] = b; acc[2][q] = b; acc[3][q] = b;
        }
    }

    const float4* A4 = reinterpret_cast<const float4*>(smf + SACT);
    #pragma unroll
    for (int k = 0; k < NIN; k++) {
        float4 a = A4[k * 64 + pg];
        ull a0 = pack2(a.x), a1 = pack2(a.y), a2 = pack2(a.z), a3 = pack2(a.w);
        const ulonglong2* wr = reinterpret_cast<const ulonglong2*>(W + k*NOUT + j0);
        #pragma unroll
        for (int q2 = 0; q2 < PAIRS/2; q2++) {
            ulonglong2 w = wr[q2];
            fma2(acc[0][2*q2],   a0, w.x); fma2(acc[0][2*q2+1], a0, w.y);
            fma2(acc[1][2*q2],   a1, w.x); fma2(acc[1][2*q2+1], a1, w.y);
            fma2(acc[2][2*q2],   a2, w.x); fma2(acc[2][2*q2+1], a2, w.y);
            fma2(acc[3][2*q2],   a3, w.x); fma2(acc[3][2*q2+1], a3, w.y);
        }
    }

    __syncthreads();   // all reads of SACT done -> safe to overwrite in place

    float4* D4 = reinterpret_cast<float4*>(smf + SACT);
    #pragma unroll
    for (int q = 0; q < PAIRS; q++) {
        float v0l = lo32(acc[0][q]), v0h = hi32(acc[0][q]);
        float v1l = lo32(acc[1][q]), v1h = hi32(acc[1][q]);
        float v2l = lo32(acc[2][q]), v2h = hi32(acc[2][q]);
        float v3l = lo32(acc[3][q]), v3h = hi32(acc[3][q]);
        if (RELU) {
            v0l = fmaxf(v0l, 0.f); v0h = fmaxf(v0h, 0.f);
            v1l = fmaxf(v1l, 0.f); v1h = fmaxf(v1h, 0.f);
            v2l = fmaxf(v2l, 0.f); v2h = fmaxf(v2h, 0.f);
            v3l = fmaxf(v3l, 0.f); v3h = fmaxf(v3h, 0.f);
        }
        D4[(j0 + 2*q)     * 64 + pg] = make_float4(v0l, v1l, v2l, v3l);
        D4[(j0 + 2*q + 1) * 64 + pg] = make_float4(v0h, v1h, v2h, v3h);
    }

    if (EMIT_SIGMA && strip == 0) {
        const int g0 = gbase + 4*pg;
        float s0 = lo32(acc[0][0]), s1 = lo32(acc[1][0]);
        float s2 = lo32(acc[2][0]), s3 = lo32(acc[3][0]);
        if (g0 + 0 < n) out[g0 + 0] = expf(s0);
        if (g0 + 1 < n) out[g0 + 1] = expf(s1);
        if (g0 + 2 < n) out[g0 + 2] = expf(s2);
        if (g0 + 3 < n) out[g0 + 3] = expf(s3);
    }
}

extern "C" __global__ void __launch_bounds__(NTHR, 2)
nerf_fused3(const float* __restrict__ gx, const float* __restrict__ gtab,
            const float* __restrict__ w_dw1, const float* __restrict__ w_db1,
            const float* __restrict__ w_dw2, const float* __restrict__ w_db2,
            const float* __restrict__ w_dw3, const float* __restrict__ w_db3,
            const float* __restrict__ w_cw1, const float* __restrict__ w_cb1,
            const float* __restrict__ w_cw2, const float* __restrict__ w_cb2,
            const float* __restrict__ w_cw3, const float* __restrict__ w_cb3,
            const float* __restrict__ w_cw4, const float* __restrict__ w_cb4,
            float* __restrict__ out, int n)
{
    extern __shared__ float smf[];
    const int tid = threadIdx.x;
    const int gbase = blockIdx.x * NPTS_CTA;

    // stage layer-1 weights (overlaps with encode)
    stage4(w_dw1, smf + SW0, 32*64, tid);
    stage4(w_db1, smf + SBI0, 64, tid);

    {
        const int p = tid;
        const int gp = gbase + p;
        const bool valid = gp < n;
        float px = 0.f, py = 0.f, pz = 0.f;
        if (valid) { px = gx[3*gp]; py = gx[3*gp+1]; pz = gx[3*gp+2]; }
        encode16(px * 0.5f + 0.5f, py * 0.5f + 0.5f, pz * 0.5f + 0.5f,
                 gtab, smf + SACT, p, valid);
    }
    __syncthreads();

    // d1: 32 -> 64 relu
    stage4(w_dw2, smf + SW1, 64*64, tid);
    stage4(w_db2, smf + SBI1, 64, tid);
    layer<32, 64, true, false>(smf, smf + SW0, smf + SBI0, tid, (float*)out, gbase, n);
    __syncthreads();

    // d2: 64 -> 64 relu
    stage4(w_dw3, smf + SW0, 64*16, tid);
    stage4(w_db3, smf + SBI0, 16, tid);
    layer<64, 64, true, false>(smf, smf + SW1, smf + SBI1, tid, (float*)out, gbase, n);
    __syncthreads();

    // d3: 64 -> 16, no relu, emits sigma
    stage4(w_cw1, smf + SW1, 16*64, tid);
    stage4(w_cb1, smf + SBI1, 64, tid);
    layer<64, 16, false, true>(smf, smf + SW0, smf + SBI0, tid, (float*)out, gbase, n);
    __syncthreads();

    // c1: 16 -> 64 relu
    stage4(w_cw2, smf + SW0, 64*64, tid);
    stage4(w_cb2, smf + SBI0, 64, tid);
    layer<16, 64, true, false>(smf, smf + SW1, smf + SBI1, tid, (float*)out, gbase, n);
    __syncthreads();

    // c2: 64 -> 64 relu
    stage4(w_cw3, smf + SW1, 64*64, tid);
    stage4(w_cb3, smf + SBI1, 64, tid);
    layer<64, 64, true, false>(smf, smf + SW0, smf + SBI0, tid, (float*)out, gbase, n);
    __syncthreads();

    // c3: 64 -> 64 relu
    stage4(w_cw4, smf + SW0, 192, tid);
    if (tid < 3) smf[SBI0 + tid] = __ldg(w_cb4 + tid);
    layer<64, 64, true, false>(smf, smf + SW1, smf + SBI1, tid, (float*)out, gbase, n);
    __syncthreads();

    // color head: 64 -> 3, sigmoid; one thread per point
    {
        const int p = tid;
        const int gp = gbase + p;
        const float* A = smf + SACT;
        const float* cw = smf + SW0;
        float s0 = smf[SBI0 + 0], s1 = smf[SBI0 + 1], s2 = smf[SBI0 + 2];
        #pragma unroll
        for (int k = 0; k < 64; k++) {
            float a = A[k * NPTS_CTA + p];
            s0 = fmaf(a, cw[3*k + 0], s0);
            s1 = fmaf(a, cw[3*k + 1], s1);
            s2 = fmaf(a, cw[3*k + 2], s2);
        }
        if (gp < n) {
            out[n + 3*gp + 0] = 1.f / (1.f + expf(-s0));
            out[n + 3*gp + 1] = 1.f / (1.f + expf(-s1));
            out[n + 3*gp + 2] = 1.f / (1.f + expf(-s2));
        }
    }
}

extern "C" void kernel_launch(void* const* d_in, const int* in_sizes, int n_in,
                              void* d_out, int out_size)
{
    const float* x    = (const float*)d_in[0];
    const float* tab  = (const float*)d_in[1];
    const float* dw1  = (const float*)d_in[2];
    const float* db1  = (const float*)d_in[3];
    const float* dw2  = (const float*)d_in[4];
    const float* db2  = (const float*)d_in[5];
    const float* dw3  = (const float*)d_in[6];
    const float* db3  = (const float*)d_in[7];
    const float* cw1  = (const float*)d_in[8];
    const float* cb1  = (const float*)d_in[9];
    const float* cw2  = (const float*)d_in[10];
    const float* cb2  = (const float*)d_in[11];
    const float* cw3  = (const float*)d_in[12];
    const float* cb3  = (const float*)d_in[13];
    const float* cw4  = (const float*)d_in[14];
    const float* cb4  = (const float*)d_in[15];

    const int n = in_sizes[0] / 3;

    static int configured = -1;
    if (configured < 0) {
        cudaFuncSetAttribute(nerf_fused3,
                             cudaFuncAttributeMaxDynamicSharedMemorySize, SMEMB);
        configured = 1;
    }

    const int blocks = (n + NPTS_CTA - 1) / NPTS_CTA;
    nerf_fused3<<<blocks, NTHR, SMEMB>>>(
        x, tab, dw1, db1, dw2, db2, dw3, db3,
        cw1, cb1, cw2, cb2, cw3, cb3, cw4, cb4,
        (float*)d_out, n);
}

// round 7
// speedup vs baseline: 1.9265x; 1.2272x over previous
#include <cuda_runtime.h>
#include <cuda_bf16.h>
#include <math.h>
#include <stdint.h>

#define NPTS 128
#define NTHR 128

// ---- smem byte offsets ----
#define WD1H 0
#define WD1L 5120
#define WD2H 10240
#define WD2L 19456
#define WD3H 28672
#define WD3L 30976
#define WC1H 33280
#define WC1L 36352
#define WC2H 39424
#define WC2L 48640
#define WC3H 57856
#define WC3L 67072
#define WHDH 76288
#define WHDL 77440
#define BIASO 78592   // floats: db1[64] db2[64] db3[16] cb1[64] cb2[64] cb3[64] hb[8]
#define ACTO  80000   // 4 warps x 32 rows x 20 words x 4B = 10240
#define SMEMB 90240
// bias float sub-offsets
#define DB1 0
#define DB2 64
#define DB3 128
#define CB1 144
#define CB2 208
#define CB3 272
#define HB  336

__device__ constexpr int RESV[16] = {16,20,25,32,40,50,64,80,101,128,161,203,256,322,406,512};

__device__ __forceinline__ uint32_t pk(float lo, float hi){
    uint32_t r; asm("cvt.rn.bf16x2.f32 %0, %1, %2;" : "=r"(r) : "f"(hi), "f"(lo)); return r;
}
__device__ __forceinline__ float blo(uint32_t v){ return __uint_as_float(v << 16); }
__device__ __forceinline__ float bhi(uint32_t v){ return __uint_as_float(v & 0xFFFF0000u); }

__device__ __forceinline__ void mmab(float* c, const uint32_t* a, uint32_t b0, uint32_t b1){
    asm volatile("mma.sync.aligned.m16n8k16.row.col.f32.bf16.bf16.f32 "
        "{%0,%1,%2,%3}, {%4,%5,%6,%7}, {%8,%9}, {%0,%1,%2,%3};"
        : "+f"(c[0]), "+f"(c[1]), "+f"(c[2]), "+f"(c[3])
        : "r"(a[0]), "r"(a[1]), "r"(a[2]), "r"(a[3]), "r"(b0), "r"(b1));
}

// stage W[K][N] f32 -> smem [n][k] bf16 hi/lo, row stride (halves)
__device__ __forceinline__ void stageW(const float* __restrict__ g, char* smc,
                                       int hOff, int lOff, int K, int N, int stride, int tid){
    const float4* g4 = (const float4*)g;
    __nv_bfloat16* H = (__nv_bfloat16*)(smc + hOff);
    __nv_bfloat16* L = (__nv_bfloat16*)(smc + lOff);
    const int tot = (K*N) >> 2;
    for (int i = tid; i < tot; i += NTHR) {
        float4 w = __ldg(g4 + i);
        int k = i / (N >> 2);
        int n0 = (i % (N >> 2)) << 2;
        float vv[4] = {w.x, w.y, w.z, w.w};
        #pragma unroll
        for (int c = 0; c < 4; c++) {
            float v = vv[c];
            __nv_bfloat16 h = __float2bfloat16(v);
            __nv_bfloat16 l = __float2bfloat16(v - __bfloat162float(h));
            H[(n0 + c)*stride + k] = h;
            L[(n0 + c)*stride + k] = l;
        }
    }
}

// one MMA layer: KS k-steps of 16, NT n-tiles of 8, bias-init accumulators.
template<int KS, int NT, bool RELU, bool UAL>
__device__ __forceinline__ void layerM(const char* smc, int hOff, int lOff, int stride,
                                       const float* bias,
                                       uint32_t ah[2][KS][4], uint32_t al[2][KS][4],
                                       float C[2][NT][4], int lane){
    const int t = lane & 3, u = lane >> 2;
    #pragma unroll
    for (int j = 0; j < NT; j++){
        float2 bb = *(const float2*)(bias + 8*j + 2*t);
        #pragma unroll
        for (int mt = 0; mt < 2; mt++){
            C[mt][j][0]=bb.x; C[mt][j][1]=bb.y; C[mt][j][2]=bb.x; C[mt][j][3]=bb.y;
        }
        #pragma unroll
        for (int s = 0; s < KS; s++){
            const int boff = ((8*j + u)*stride + 16*s + 2*t)*2;
            uint32_t bh0 = *(const uint32_t*)(smc + hOff + boff);
            uint32_t bh1 = *(const uint32_t*)(smc + hOff + boff + 16);
            uint32_t bl0 = *(const uint32_t*)(smc + lOff + boff);
            uint32_t bl1 = *(const uint32_t*)(smc + lOff + boff + 16);
            #pragma unroll
            for (int mt = 0; mt < 2; mt++){
                mmab(C[mt][j], ah[mt][s], bh0, bh1);
                if (UAL) mmab(C[mt][j], al[mt][s], bh0, bh1);
                mmab(C[mt][j], ah[mt][s], bl0, bl1);
            }
        }
        if (RELU){
            #pragma unroll
            for (int mt = 0; mt < 2; mt++)
                #pragma unroll
                for (int q = 0; q < 4; q++) C[mt][j][q] = fmaxf(C[mt][j][q], 0.f);
        }
    }
}

// convert C frags (2*KSN n-tiles) -> next-layer A frags (KSN k-steps), hi/lo bf16
template<int KSN, int NTS>
__device__ __forceinline__ void convA(const float C[2][NTS][4],
                                      uint32_t ah[2][KSN][4], uint32_t al[2][KSN][4]){
    #pragma unroll
    for (int mt = 0; mt < 2; mt++)
        #pragma unroll
        for (int s = 0; s < KSN; s++){
            const float* c0 = C[mt][2*s];
            const float* c1 = C[mt][2*s+1];
            uint32_t h0 = pk(c0[0], c0[1]);
            uint32_t h1 = pk(c0[2], c0[3]);
            uint32_t h2 = pk(c1[0], c1[1]);
            uint32_t h3 = pk(c1[2], c1[3]);
            ah[mt][s][0]=h0; ah[mt][s][1]=h1; ah[mt][s][2]=h2; ah[mt][s][3]=h3;
            al[mt][s][0] = pk(c0[0]-blo(h0), c0[1]-bhi(h0));
            al[mt][s][1] = pk(c0[2]-blo(h1), c0[3]-bhi(h1));
            al[mt][s][2] = pk(c1[0]-blo(h2), c1[1]-bhi(h2));
            al[mt][s][3] = pk(c1[2]-blo(h3), c1[3]-bhi(h3));
        }
}

__device__ __forceinline__ float sg(float x){ return 1.f/(1.f + expf(-x)); }

extern "C" __global__ void __launch_bounds__(NTHR)
nerf_mma(const float* __restrict__ gx, const float* __restrict__ gtab,
         const float* __restrict__ dw1, const float* __restrict__ db1,
         const float* __restrict__ dw2, const float* __restrict__ db2,
         const float* __restrict__ dw3, const float* __restrict__ db3,
         const float* __restrict__ cw1, const float* __restrict__ cb1,
         const float* __restrict__ cw2, const float* __restrict__ cb2,
         const float* __restrict__ cw3, const float* __restrict__ cb3,
         const float* __restrict__ cw4, const float* __restrict__ cb4,
         float* __restrict__ out, int n)
{
    extern __shared__ char smc[];
    const int tid = threadIdx.x;
    const int lane = tid & 31, warp = tid >> 5;
    const int t = lane & 3, u = lane >> 2;
    const int gbase = blockIdx.x * NPTS;

    // ---- stage all weights (transposed, bf16 hi/lo) ----
    stageW(dw1, smc, WD1H, WD1L, 32, 64, 40, tid);
    stageW(dw2, smc, WD2H, WD2L, 64, 64, 72, tid);
    stageW(dw3, smc, WD3H, WD3L, 64, 16, 72, tid);
    stageW(cw1, smc, WC1H, WC1L, 16, 64, 24, tid);
    stageW(cw2, smc, WC2H, WC2L, 64, 64, 72, tid);
    stageW(cw3, smc, WC3H, WC3L, 64, 64, 72, tid);
    // head weights: zero-pad [8][72] then fill rows 0..2 with cw4^T
    for (int i = tid; i < 576; i += NTHR) ((uint32_t*)(smc + WHDH))[i] = 0u;
    __syncthreads();   // zero-fill before scatter (different threads' regions overlap)
    if (tid < 64) {
        __nv_bfloat16* H = (__nv_bfloat16*)(smc + WHDH);
        __nv_bfloat16* L = (__nv_bfloat16*)(smc + WHDL);
        #pragma unroll
        for (int c = 0; c < 3; c++) {
            float v = __ldg(&cw4[tid*3 + c]);
            __nv_bfloat16 h = __float2bfloat16(v);
            H[c*72 + tid] = h;
            L[c*72 + tid] = __float2bfloat16(v - __bfloat162float(h));
        }
    }
    // biases
    {
        float* bs = (float*)(smc + BIASO);
        if (tid < 64) {
            bs[DB1 + tid] = __ldg(db1 + tid);
            bs[DB2 + tid] = __ldg(db2 + tid);
            bs[CB1 + tid] = __ldg(cb1 + tid);
            bs[CB2 + tid] = __ldg(cb2 + tid);
            bs[CB3 + tid] = __ldg(cb3 + tid);
            if (tid < 16) bs[DB3 + tid] = __ldg(db3 + tid);
            if (tid < 8)  bs[HB + tid] = (tid < 3) ? __ldg(cb4 + tid) : 0.f;
        }
    }

    // ---- hash-grid encode: thread encodes its own point -> per-warp act array ----
    {
        const int gp = gbase + tid;
        const bool valid = gp < n;
        float px = 0.f, py = 0.f, pz = 0.f;
        if (valid) { px = gx[3*gp]; py = gx[3*gp+1]; pz = gx[3*gp+2]; }
        const float ux = px*0.5f + 0.5f, uy = py*0.5f + 0.5f, uz = pz*0.5f + 0.5f;
        uint32_t* actw = (uint32_t*)(smc + ACTO) + warp*640 + lane*20;
        #pragma unroll
        for (int l = 0; l < 16; l++) {
            const int res = RESV[l];
            const bool dense = ((long long)res*res*res) <= 65536LL;
            float f0 = 0.f, f1 = 0.f;
            if (valid) {
                const float rm1 = (float)(res - 1);
                float qx = ux*rm1, qy = uy*rm1, qz = uz*rm1;
                int cx = (int)floorf(qx); cx = max(0, min(cx, res-2));
                int cy = (int)floorf(qy); cy = max(0, min(cy, res-2));
                int cz = (int)floorf(qz); cz = max(0, min(cz, res-2));
                float wx = qx-(float)cx, wy = qy-(float)cy, wz = qz-(float)cz;
                float mx = 1.f-wx, my = 1.f-wy, mz = 1.f-wz;
                const float2* tab = (const float2*)gtab + ((size_t)l << 16);
                #pragma unroll
                for (int c8 = 0; c8 < 8; c8++) {
                    const int ox=(c8>>2)&1, oy=(c8>>1)&1, oz=c8&1;
                    const unsigned ix=(unsigned)(cx+ox), iy=(unsigned)(cy+oy), iz=(unsigned)(cz+oz);
                    const float wc = (ox?wx:mx)*(oy?wy:my)*(oz?wz:mz);
                    unsigned idx;
                    if (dense) idx = ix + (unsigned)res*(iy + (unsigned)res*iz);
                    else       idx = (ix*1u ^ iy*2654435761u ^ iz*805459861u) & 65535u;
                    const float2 e = __ldg(tab + idx);
                    f0 = fmaf(wc, e.x, f0);
                    f1 = fmaf(wc, e.y, f1);
                }
            }
            actw[l] = pk(f0, f1);   // cols (2l, 2l+1) as bf16x2
        }
    }
    __syncthreads();

    const float* bs = (const float*)(smc + BIASO);
    uint32_t ah[2][4][4], al[2][4][4];
    float Ca[2][8][4], Cb[2][8][4];

    // ---- d1: 32 -> 64 relu (A from encode, hi only; W hi/lo) ----
    {
        const uint32_t* act = (const uint32_t*)(smc + ACTO) + warp*640;
        uint32_t ah1[2][2][4];
        #pragma unroll
        for (int mt = 0; mt < 2; mt++)
            #pragma unroll
            for (int s = 0; s < 2; s++) {
                ah1[mt][s][0] = act[(mt*16 + u)*20     + 8*s + t];
                ah1[mt][s][1] = act[(mt*16 + u + 8)*20 + 8*s + t];
                ah1[mt][s][2] = act[(mt*16 + u)*20     + 8*s + 4 + t];
                ah1[mt][s][3] = act[(mt*16 + u + 8)*20 + 8*s + 4 + t];
            }
        layerM<2,8,true,false>(smc, WD1H, WD1L, 40, bs + DB1, ah1, ah1, Ca, lane);
    }

    // ---- d2: 64 -> 64 relu ----
    convA<4,8>(Ca, ah, al);
    layerM<4,8,true,true>(smc, WD2H, WD2L, 72, bs + DB2, ah, al, Cb, lane);

    // ---- d3: 64 -> 16 (no relu) + sigma ----
    float Cd[2][2][4];
    convA<4,8>(Cb, ah, al);
    layerM<4,2,false,true>(smc, WD3H, WD3L, 72, bs + DB3, ah, al, Cd, lane);
    if (t == 0) {
        #pragma unroll
        for (int mt = 0; mt < 2; mt++) {
            int g = gbase + warp*32 + mt*16 + u;
            if (g < n)     out[g]     = expf(Cd[mt][0][0]);
            if (g + 8 < n) out[g + 8] = expf(Cd[mt][0][2]);
        }
    }

    // ---- c1: 16 -> 64 relu ----
    {
        uint32_t ah1[2][1][4], al1[2][1][4];
        convA<1,2>(Cd, ah1, al1);
        layerM<1,8,true,true>(smc, WC1H, WC1L, 24, bs + CB1, ah1, al1, Ca, lane);
    }

    // ---- c2: 64 -> 64 relu ----
    convA<4,8>(Ca, ah, al);
    layerM<4,8,true,true>(smc, WC2H, WC2L, 72, bs + CB2, ah, al, Cb, lane);

    // ---- c3: 64 -> 64 relu ----
    convA<4,8>(Cb, ah, al);
    layerM<4,8,true,true>(smc, WC3H, WC3L, 72, bs + CB3, ah, al, Ca, lane);

    // ---- color head: 64 -> 3(pad 8), sigmoid ----
    {
        float Ch[2][1][4];
        convA<4,8>(Ca, ah, al);
        layerM<4,1,false,true>(smc, WHDH, WHDL, 72, bs + HB, ah, al, Ch, lane);
        #pragma unroll
        for (int mt = 0; mt < 2; mt++) {
            int g0 = gbase + warp*32 + mt*16 + u;
            int g1 = g0 + 8;
            if (t == 0) {
                if (g0 < n) {
                    out[n + 3*g0 + 0] = sg(Ch[mt][0][0]);
                    out[n + 3*g0 + 1] = sg(Ch[mt][0][1]);
                }
                if (g1 < n) {
                    out[n + 3*g1 + 0] = sg(Ch[mt][0][2]);
                    out[n + 3*g1 + 1] = sg(Ch[mt][0][3]);
                }
            } else if (t == 1) {
                if (g0 < n) out[n + 3*g0 + 2] = sg(Ch[mt][0][0]);
                if (g1 < n) out[n + 3*g1 + 2] = sg(Ch[mt][0][2]);
            }
        }
    }
}

extern "C" void kernel_launch(void* const* d_in, const int* in_sizes, int n_in,
                              void* d_out, int out_size)
{
    const int n = in_sizes[0] / 3;
    static int cfg = 0;
    if (!cfg) {
        cudaFuncSetAttribute(nerf_mma, cudaFuncAttributeMaxDynamicSharedMemorySize, SMEMB);
        cfg = 1;
    }
    const int blocks = (n + NPTS - 1) / NPTS;
    nerf_mma<<<blocks, NTHR, SMEMB>>>(
        (const float*)d_in[0], (const float*)d_in[1],
        (const float*)d_in[2], (const float*)d_in[3],
        (const float*)d_in[4], (const float*)d_in[5],
        (const float*)d_in[6], (const float*)d_in[7],
        (const float*)d_in[8], (const float*)d_in[9],
        (const float*)d_in[10], (const float*)d_in[11],
        (const float*)d_in[12], (const float*)d_in[13],
        (const float*)d_in[14], (const float*)d_in[15],
        (float*)d_out, n);
}